// round 17
// baseline (speedup 1.0000x reference)
#include <cuda_runtime.h>
#include <cuda_fp16.h>
#include <math.h>
#include <stdint.h>

#define BATCH   4
#define SEQLEN  2048
#define NHEADS  16
#define HDIM    64
#define DIM     1024
#define MTOT    (BATCH * SEQLEN)   // 8192
#define KW      (DIM / 2)          // 512 packed words per token row

// ---------------- scratch (static __device__, no allocs allowed) -------------
__device__ uint32_t g_xh[MTOT * KW];                 // x (A-side, hi only)
__device__ uint32_t g_qh[MTOT * KW];                 // Q hi only
__device__ uint32_t g_kh[MTOT * KW];                 // K hi only
__device__ uint32_t g_vh[MTOT * KW];                 // V hi only
__device__ uint32_t g_ah[MTOT * KW];                 // attn out (A-side, hi only)
__device__ uint32_t g_wqh[DIM * KW];                 // all weights: hi only
__device__ uint32_t g_wkh[DIM * KW];
__device__ uint32_t g_wvh[DIM * KW];
__device__ uint32_t g_woh[DIM * KW];

// ---------------- fp16x2 helpers ---------------------------------------------
__device__ __forceinline__ uint32_t pack2h(float lo, float hi) {
    uint32_t r;
    asm("cvt.rn.f16x2.f32 %0, %1, %2;" : "=r"(r) : "f"(hi), "f"(lo));
    return r;
}
__device__ __forceinline__ uint32_t prmtw(uint32_t a, uint32_t b, uint32_t sel) {
    uint32_t d;
    asm("prmt.b32 %0, %1, %2, %3;" : "=r"(d) : "r"(a), "r"(b), "r"(sel));
    return d;
}
__device__ __forceinline__ void mma16h(float* d, const uint32_t* a, const uint32_t* b) {
    asm volatile(
        "mma.sync.aligned.m16n8k16.row.col.f32.f16.f16.f32 "
        "{%0,%1,%2,%3}, {%4,%5,%6,%7}, {%8,%9}, {%0,%1,%2,%3};"
        : "+f"(d[0]), "+f"(d[1]), "+f"(d[2]), "+f"(d[3])
        : "r"(a[0]), "r"(a[1]), "r"(a[2]), "r"(a[3]), "r"(b[0]), "r"(b[1]));
}
__device__ __forceinline__ void ldsm_x4(uint32_t* r, uint32_t saddr) {
    asm volatile("ldmatrix.sync.aligned.m8n8.x4.shared.b16 {%0,%1,%2,%3}, [%4];"
        : "=r"(r[0]), "=r"(r[1]), "=r"(r[2]), "=r"(r[3]) : "r"(saddr));
}
__device__ __forceinline__ void ldsm_x2(uint32_t* r, uint32_t saddr) {
    asm volatile("ldmatrix.sync.aligned.m8n8.x2.shared.b16 {%0,%1}, [%2];"
        : "=r"(r[0]), "=r"(r[1]) : "r"(saddr));
}
__device__ __forceinline__ uint32_t smem_u32(const void* p) {
    uint32_t a;
    asm("{ .reg .u64 t; cvta.to.shared.u64 t, %1; cvt.u32.u64 %0, t; }" : "=r"(a) : "l"(p));
    return a;
}
#define CP16(saddr, gptr) \
    asm volatile("cp.async.cg.shared.global [%0], [%1], 16;" :: "r"(saddr), "l"(gptr))
#define CP_COMMIT() asm volatile("cp.async.commit_group;" ::: "memory")
#define CP_WAIT0()  asm volatile("cp.async.wait_group 0;" ::: "memory")

// ---------------- prepack kernels --------------------------------------------
__global__ void prepack_hi(const float* __restrict__ src, uint32_t* __restrict__ hi, int nwords)
{
    int i = blockIdx.x * blockDim.x + threadIdx.x;
    int stride = gridDim.x * blockDim.x;
    for (; i < nwords; i += stride) {
        float2 v = ((const float2*)src)[i];
        hi[i] = pack2h(v.x, v.y);
    }
}
// all four weight matrices in one launch (each DIM*KW = 2^19 words)
__global__ void prepack_w4(const float* __restrict__ s0, const float* __restrict__ s1,
                           const float* __restrict__ s2, const float* __restrict__ s3,
                           uint32_t* __restrict__ d0, uint32_t* __restrict__ d1,
                           uint32_t* __restrict__ d2, uint32_t* __restrict__ d3)
{
    const int N = DIM * KW;                       // 524288 = 1<<19
    int i = blockIdx.x * blockDim.x + threadIdx.x;
    int stride = gridDim.x * blockDim.x;
    for (; i < 4 * N; i += stride) {
        const int region = i >> 19;
        const int off = i & (N - 1);
        const float* s = (region == 0) ? s0 : (region == 1) ? s1 : (region == 2) ? s2 : s3;
        uint32_t* d    = (region == 0) ? d0 : (region == 1) ? d1 : (region == 2) ? d2 : d3;
        float2 v = ((const float2*)s)[off];
        d[off] = pack2h(v.x, v.y);
    }
}

// ---------------- GEMM: C[m][n] = sum_k A[m][k]*B[n][k]  (NT) ----------------
// CTA 128x128x32, 4 warps of 64x64. fp16 hi-only single pass, ldmatrix frags.
#define RSTR 20                          // words/row: 16 kwords + 4 pad
#define GARR (128 * RSTR)                // 2560 words per array
#define GEMM_SMEM_BYTES (2 * 2 * GARR * 4)   // 40960

__global__ void __launch_bounds__(128, 3)
gemm_h(const uint32_t* __restrict__ Ahg,
       const uint32_t* __restrict__ Bh0, const uint32_t* __restrict__ Bh1,
       const uint32_t* __restrict__ Bh2,
       uint32_t* __restrict__ O0, uint32_t* __restrict__ O1, uint32_t* __restrict__ O2,
       float* __restrict__ Cf)
{
    const uint32_t* Bhg = (blockIdx.z == 0) ? Bh0 : (blockIdx.z == 1 ? Bh1 : Bh2);

    extern __shared__ uint32_t gsm[];
    const uint32_t sbase = smem_u32(gsm);
    const int tid  = threadIdx.x;
    const int lane = tid & 31;
    const int wid  = tid >> 5;
    const int g    = lane >> 2;
    const int t    = lane & 3;
    const int wm   = wid >> 1;
    const int wn   = wid & 1;
    const size_t m0 = blockIdx.y * 128;
    const size_t n0 = blockIdx.x * 128;

    const int lr  = tid >> 2;            // 0..31
    const int cw4 = (tid & 3) * 4;       // kword offset

    // ldmatrix per-lane word offsets (within stage arrays)
    const int aoff = (wm * 64 + (lane & 15)) * RSTR + (lane >> 4) * 4;
    const int boff = (wn * 64 + (lane & 7)) * RSTR + ((lane >> 3) & 1) * 4;

    float acc[4][8][4];
#pragma unroll
    for (int i = 0; i < 4; i++)
#pragma unroll
        for (int j = 0; j < 8; j++)
#pragma unroll
            for (int c = 0; c < 4; c++) acc[i][j][c] = 0.f;

    const int NT = DIM / 32;

    auto load_stage = [&](int buf, int kw0) {
        const uint32_t sb = sbase + (uint32_t)buf * 2 * GARR * 4;
#pragma unroll
        for (int p = 0; p < 4; p++) {
            const int r = lr + p * 32;
            const int widx = r * RSTR + cw4;
            CP16(sb + widx * 4,          Ahg + (m0 + r) * KW + kw0 + cw4);
            CP16(sb + (GARR + widx) * 4, Bhg + (n0 + r) * KW + kw0 + cw4);
        }
    };

    load_stage(0, 0);
    CP_COMMIT();

    for (int kt = 0; kt < NT; kt++) {
        CP_WAIT0();
        __syncthreads();
        if (kt + 1 < NT) {
            load_stage((kt + 1) & 1, (kt + 1) * 16);
            CP_COMMIT();
        }

        const uint32_t stage_b = sbase + (uint32_t)(kt & 1) * 2 * GARR * 4;

#pragma unroll
        for (int ck = 0; ck < 2; ck++) {
            uint32_t a[4][4];
#pragma unroll
            for (int mi = 0; mi < 4; mi++)
                ldsm_x4(a[mi], stage_b + (uint32_t)(aoff + mi * 16 * RSTR + ck * 8) * 4);
#pragma unroll
            for (int nj = 0; nj < 8; nj++) {
                uint32_t bh[2];
                ldsm_x2(bh, stage_b + (uint32_t)(GARR + boff + nj * 8 * RSTR + ck * 8) * 4);
#pragma unroll
                for (int mi = 0; mi < 4; mi++) mma16h(acc[mi][nj], a[mi], bh);
            }
        }
    }

    // ---- epilogue ----
    if (Cf) {
#pragma unroll
        for (int mi = 0; mi < 4; mi++) {
#pragma unroll
            for (int nj = 0; nj < 8; nj++) {
                const int row = (int)m0 + wm * 64 + mi * 16 + g;
                const int col = (int)n0 + wn * 64 + nj * 8 + 2 * t;
                *(float2*)(Cf + (size_t)row * DIM + col)       = make_float2(acc[mi][nj][0], acc[mi][nj][1]);
                *(float2*)(Cf + (size_t)(row + 8) * DIM + col) = make_float2(acc[mi][nj][2], acc[mi][nj][3]);
            }
        }
    } else {
        uint32_t* Oh = (blockIdx.z == 0) ? O0 : (blockIdx.z == 1 ? O1 : O2);
#pragma unroll
        for (int mi = 0; mi < 4; mi++) {
#pragma unroll
            for (int nj = 0; nj < 8; nj++) {
                const int row = (int)m0 + wm * 64 + mi * 16 + g;
                const int wc  = (int)(n0 >> 1) + wn * 32 + nj * 4 + t;
                Oh[(size_t)row * KW + wc]       = pack2h(acc[mi][nj][0], acc[mi][nj][1]);
                Oh[(size_t)(row + 8) * KW + wc] = pack2h(acc[mi][nj][2], acc[mi][nj][3]);
            }
        }
    }
}

// ---------------- Flash attention (plain fp16 mma) with diagonal mask --------
// QK single pass (Q frags register-resident, K frags via ldmatrix.x2);
// PV single pass. K/V double-buffered, one sync per tile.
#define BQ 128
#define BS 64
#define KS 36
#define VS 72
#define KBUF (BS * KS)   // 2304 words per K buffer
#define VBUF (32 * VS)   // 2304 words per V buffer
#define ATTN_SMEM_WORDS (2 * KBUF + 2 * VBUF)
#define ATTN_SMEM_BYTES (ATTN_SMEM_WORDS * 4)   // 36864

__global__ void __launch_bounds__(256, 2)
attn_kernel(const uint32_t* __restrict__ Qhg,
            const uint32_t* __restrict__ Khg, const uint32_t* __restrict__ Vhg,
            uint32_t* __restrict__ Ohg)
{
    extern __shared__ uint32_t smw[];
    uint32_t* Kb = smw;                     // 2 x [64][KS]
    uint32_t* Vb = Kb + 2 * KBUF;           // 2 x [32][VS]
    const uint32_t sbase = smem_u32(smw);

    const int tid  = threadIdx.x;
    const int lane = tid & 31;
    const int wid  = tid >> 5;
    const int g    = lane >> 2;
    const int t    = lane & 3;
    const int q0   = blockIdx.x * BQ;
    const int bh_i = blockIdx.y;
    const int b    = bh_i >> 4;
    const int h    = bh_i & 15;
    const float scale = 0.125f;

    const size_t rowbase = (size_t)b * SEQLEN;
    const int hw = h * 32;

    // loader lane mapping
    const int kr_r  = tid >> 2;          // K: row 0..63
    const int kr_cw = (tid & 3) * 8;     // K: 8 words
    const int v_s2  = tid >> 3;          // V: sword 0..31
    const int v_db  = (tid & 7) * 8;     // V: d offset

    // ldmatrix lane offset for K fragments (within one K buffer)
    const int koff = (lane & 7) * KS + ((lane >> 3) & 1) * 4;

    const int rq = wid * 16;

    // ---- Q fragments: register-resident hi-only, loaded once from gmem ----
    uint32_t qf[4][4];
    {
        const size_t r0 = (rowbase + q0 + rq + g) * KW + hw;
        const size_t r1 = (rowbase + q0 + rq + g + 8) * KW + hw;
#pragma unroll
        for (int ks = 0; ks < 4; ks++) {
            const int kwb = ks * 8;
            qf[ks][0] = Qhg[r0 + kwb + t];
            qf[ks][1] = Qhg[r1 + kwb + t];
            qf[ks][2] = Qhg[r0 + kwb + t + 4];
            qf[ks][3] = Qhg[r1 + kwb + t + 4];
        }
    }

    float mrow[2], lrow[2], O[8][4];
    mrow[0] = mrow[1] = -1e30f;
    lrow[0] = lrow[1] = 0.f;
#pragma unroll
    for (int nt = 0; nt < 8; nt++)
#pragma unroll
        for (int c = 0; c < 4; c++) O[nt][c] = 0.f;

    // ---- tile 0 load + store to buffer 0 ----
    {
        const uint32_t* kr = Khg + (rowbase + kr_r) * KW + hw + kr_cw;
        uint4 k0 = *(const uint4*)kr;
        uint4 k1 = *(const uint4*)(kr + 4);
        const uint32_t* vp = Vhg + (rowbase + 2 * v_s2) * KW + hw + v_db / 2;
        uint4 w0 = *(const uint4*)vp;
        uint4 w1 = *(const uint4*)(vp + KW);
        *(uint4*)&Kb[kr_r * KS + kr_cw]     = k0;
        *(uint4*)&Kb[kr_r * KS + kr_cw + 4] = k1;
        uint4 o0, o1;
        o0.x = prmtw(w0.x, w1.x, 0x5410); o0.y = prmtw(w0.x, w1.x, 0x7632);
        o0.z = prmtw(w0.y, w1.y, 0x5410); o0.w = prmtw(w0.y, w1.y, 0x7632);
        o1.x = prmtw(w0.z, w1.z, 0x5410); o1.y = prmtw(w0.z, w1.z, 0x7632);
        o1.z = prmtw(w0.w, w1.w, 0x5410); o1.w = prmtw(w0.w, w1.w, 0x7632);
        *(uint4*)&Vb[v_s2 * VS + v_db]     = o0;
        *(uint4*)&Vb[v_s2 * VS + v_db + 4] = o1;
    }
    __syncthreads();

    const int NTILES = SEQLEN / BS;
    for (int it = 0; it < NTILES; it++) {
        const int s0 = it * BS;
        const bool has = (it + 1 < NTILES);
        const uint32_t kbb = sbase + (uint32_t)(it & 1) * KBUF * 4;   // K buffer byte base
        const uint32_t* Vhi = Vb + (it & 1) * VBUF;

        // prefetch next tile into registers (overlaps with compute)
        uint4 nk0, nk1, nw0, nw1;
        if (has) {
            const uint32_t* kr = Khg + (rowbase + s0 + BS + kr_r) * KW + hw + kr_cw;
            nk0 = *(const uint4*)kr;
            nk1 = *(const uint4*)(kr + 4);
            const uint32_t* vp = Vhg + (rowbase + s0 + BS + 2 * v_s2) * KW + hw + v_db / 2;
            nw0 = *(const uint4*)vp;
            nw1 = *(const uint4*)(vp + KW);
        }

        // ---- S = Q @ K^T  (single pass, Q regs, K via ldmatrix) ----
        float S[8][4];
#pragma unroll
        for (int nt = 0; nt < 8; nt++)
#pragma unroll
            for (int c = 0; c < 4; c++) S[nt][c] = 0.f;

#pragma unroll
        for (int ks = 0; ks < 4; ks++) {
#pragma unroll
            for (int nt = 0; nt < 8; nt++) {
                uint32_t bfr[2];
                ldsm_x2(bfr, kbb + (uint32_t)(koff + nt * 8 * KS + ks * 8) * 4);
                mma16h(S[nt], qf[ks], bfr);
            }
        }

        // ---- scale + diagonal mask ----
#pragma unroll
        for (int nt = 0; nt < 8; nt++) {
#pragma unroll
            for (int c = 0; c < 4; c++) {
                const int col = s0 + nt * 8 + 2 * t + (c & 1);
                const int row = q0 + rq + g + ((c >= 2) ? 8 : 0);
                float s = S[nt][c] * scale;
                if (col == row) s = -1e30f;
                S[nt][c] = s;
            }
        }

        // ---- online softmax ----
        float mx0 = -1e30f, mx1 = -1e30f;
#pragma unroll
        for (int nt = 0; nt < 8; nt++) {
            mx0 = fmaxf(mx0, fmaxf(S[nt][0], S[nt][1]));
            mx1 = fmaxf(mx1, fmaxf(S[nt][2], S[nt][3]));
        }
        mx0 = fmaxf(mx0, __shfl_xor_sync(0xffffffffu, mx0, 1));
        mx0 = fmaxf(mx0, __shfl_xor_sync(0xffffffffu, mx0, 2));
        mx1 = fmaxf(mx1, __shfl_xor_sync(0xffffffffu, mx1, 1));
        mx1 = fmaxf(mx1, __shfl_xor_sync(0xffffffffu, mx1, 2));

        const float mn0 = fmaxf(mrow[0], mx0);
        const float mn1 = fmaxf(mrow[1], mx1);
        const float corr0 = __expf(mrow[0] - mn0);
        const float corr1 = __expf(mrow[1] - mn1);
        mrow[0] = mn0; mrow[1] = mn1;

        float rs0 = 0.f, rs1 = 0.f;
#pragma unroll
        for (int nt = 0; nt < 8; nt++) {
            float p0 = __expf(S[nt][0] - mn0);
            float p1 = __expf(S[nt][1] - mn0);
            float p2 = __expf(S[nt][2] - mn1);
            float p3 = __expf(S[nt][3] - mn1);
            S[nt][0] = p0; S[nt][1] = p1; S[nt][2] = p2; S[nt][3] = p3;
            rs0 += p0 + p1;
            rs1 += p2 + p3;
        }
        rs0 += __shfl_xor_sync(0xffffffffu, rs0, 1);
        rs0 += __shfl_xor_sync(0xffffffffu, rs0, 2);
        rs1 += __shfl_xor_sync(0xffffffffu, rs1, 1);
        rs1 += __shfl_xor_sync(0xffffffffu, rs1, 2);

        lrow[0] = lrow[0] * corr0 + rs0;
        lrow[1] = lrow[1] * corr1 + rs1;
#pragma unroll
        for (int nt = 0; nt < 8; nt++) {
            O[nt][0] *= corr0; O[nt][1] *= corr0;
            O[nt][2] *= corr1; O[nt][3] *= corr1;
        }

        // ---- O += P @ V : single pass (P hi only) ----
#pragma unroll
        for (int ks = 0; ks < 4; ks++) {
            uint32_t ph[4];
            ph[0] = pack2h(S[2 * ks][0],     S[2 * ks][1]);
            ph[1] = pack2h(S[2 * ks][2],     S[2 * ks][3]);
            ph[2] = pack2h(S[2 * ks + 1][0], S[2 * ks + 1][1]);
            ph[3] = pack2h(S[2 * ks + 1][2], S[2 * ks + 1][3]);
            const int swb = ks * 8;
#pragma unroll
            for (int nt = 0; nt < 8; nt++) {
                uint32_t vfr[2];
                vfr[0] = Vhi[(swb + t) * VS + nt * 8 + g];
                vfr[1] = Vhi[(swb + t + 4) * VS + nt * 8 + g];
                mma16h(O[nt], ph, vfr);
            }
        }

        // ---- store prefetched tile into the other buffer ----
        if (has) {
            uint32_t* Kn = Kb + ((it + 1) & 1) * KBUF;
            uint32_t* Vn = Vb + ((it + 1) & 1) * VBUF;
            *(uint4*)&Kn[kr_r * KS + kr_cw]     = nk0;
            *(uint4*)&Kn[kr_r * KS + kr_cw + 4] = nk1;
            uint4 o0, o1;
            o0.x = prmtw(nw0.x, nw1.x, 0x5410); o0.y = prmtw(nw0.x, nw1.x, 0x7632);
            o0.z = prmtw(nw0.y, nw1.y, 0x5410); o0.w = prmtw(nw0.y, nw1.y, 0x7632);
            o1.x = prmtw(nw0.z, nw1.z, 0x5410); o1.y = prmtw(nw0.z, nw1.z, 0x7632);
            o1.z = prmtw(nw0.w, nw1.w, 0x5410); o1.w = prmtw(nw0.w, nw1.w, 0x7632);
            *(uint4*)&Vn[v_s2 * VS + v_db]     = o0;
            *(uint4*)&Vn[v_s2 * VS + v_db + 4] = o1;
        }
        __syncthreads();
    }

    // ---- finalize: write packed fp16 hi words for wo GEMM ----
    const float inv0 = 1.f / lrow[0];
    const float inv1 = 1.f / lrow[1];
#pragma unroll
    for (int nt = 0; nt < 8; nt++) {
        const int row = q0 + rq + g;
        const int wc  = hw + nt * 4 + t;
        Ohg[(rowbase + row) * KW + wc]     = pack2h(O[nt][0] * inv0, O[nt][1] * inv0);
        Ohg[(rowbase + row + 8) * KW + wc] = pack2h(O[nt][2] * inv1, O[nt][3] * inv1);
    }
}

// ---------------- launch ------------------------------------------------------
extern "C" void kernel_launch(void* const* d_in, const int* in_sizes, int n_in,
                              void* d_out, int out_size)
{
    (void)in_sizes; (void)n_in; (void)out_size;
    const float* x  = (const float*)d_in[0];
    const float* wq = (const float*)d_in[1];
    const float* wk = (const float*)d_in[2];
    const float* wv = (const float*)d_in[3];
    const float* wo = (const float*)d_in[4];
    float* out = (float*)d_out;

    uint32_t *xh, *qh, *kh, *vh, *ah;
    uint32_t *wqh, *wkh, *wvh, *woh;
    cudaGetSymbolAddress((void**)&xh, g_xh);
    cudaGetSymbolAddress((void**)&qh, g_qh);
    cudaGetSymbolAddress((void**)&kh, g_kh);  cudaGetSymbolAddress((void**)&vh, g_vh);
    cudaGetSymbolAddress((void**)&ah, g_ah);
    cudaGetSymbolAddress((void**)&wqh, g_wqh);
    cudaGetSymbolAddress((void**)&wkh, g_wkh);
    cudaGetSymbolAddress((void**)&wvh, g_wvh);
    cudaGetSymbolAddress((void**)&woh, g_woh);

    cudaFuncSetAttribute(gemm_h, cudaFuncAttributeMaxDynamicSharedMemorySize, GEMM_SMEM_BYTES);
    cudaFuncSetAttribute(attn_kernel, cudaFuncAttributeMaxDynamicSharedMemorySize, ATTN_SMEM_BYTES);

    // 0) prepack x + all weights (2 launches)
    prepack_hi<<<2048, 256>>>(x, xh, MTOT * KW);
    prepack_w4<<<2048, 256>>>(wq, wk, wv, wo, wqh, wkh, wvh, woh);

    // 1) QKV projections, single-pass B (fused via grid.z)
    {
        dim3 grid(DIM / 128, MTOT / 128, 3);
        gemm_h<<<grid, 128, GEMM_SMEM_BYTES>>>(xh,
                                               wqh, wkh, wvh,
                                               qh, kh, vh, nullptr);
    }
    // 2) attention (packed in, packed out)
    {
        dim3 grid(SEQLEN / BQ, BATCH * NHEADS);
        attn_kernel<<<grid, 256, ATTN_SMEM_BYTES>>>(qh, kh, vh, ah);
    }
    // 3) output projection, single-pass B -> fp32 out
    {
        dim3 grid(DIM / 128, MTOT / 128, 1);
        gemm_h<<<grid, 128, GEMM_SMEM_BYTES>>>(ah,
                                               woh, woh, woh,
                                               nullptr, nullptr, nullptr,
                                               out);
    }
}